// round 12
// baseline (speedup 1.0000x reference)
#include <cuda_runtime.h>
#include <math.h>

#define BB 16
#define NN 8400
#define GG 128
#define NCL 5
#define BN (BB*NN)      // 134400
#define BGT (BB*GG)     // 2048
#define NQ4 (NN/4)      // 2100 float4s per row
#define MAXTK 18
#define EPSF 1e-9f
#define HPI_F 1.57079632679489662f
#define PI_F  3.14159265358979323f
#define IPI_F 0.318309886183790672f

typedef unsigned long long u64;

struct GTC {
    float gx, gy, ct, st;
    float w15, h15, inv_s2, inv_sc2;
    float factor, gth;
    int budget, fbk, flags, lbl;
    float pad0, pad1;
};

__device__ GTC           d_gt[BGT];
__device__ float         d_am[(size_t)BGT * NN];  // [b][g][n]
__device__ u64           d_best[BN];              // (val<<32)|(127-g)
__device__ int           d_norm[BN];
__device__ unsigned char d_pos[BN];
__device__ int           d_cnt[BGT];              // nonzero in-center flag

// ---------------------------------------------------------------------------
__global__ __launch_bounds__(256) void prep_gt(const int* __restrict__ gl,
                                               const float* __restrict__ gb,
                                               const float* __restrict__ mg) {
    int bg = blockIdx.x * 256 + threadIdx.x;
    if (bg >= BGT) return;
    const float* g = gb + (size_t)bg * 5;
    float gx = g[0], gy = g[1], w = g[2], h = g[3], th = g[4];
    float wc = fmaxf(w, EPSF), hc = fmaxf(h, EPSF);
    float area = wc * hc;
    float ar = fmaxf(wc / hc, hc / wc);
    float sev = fminf(fmaxf((0.01f - area) / (0.01f + EPSF), 0.f), 1.f);
    int te = (int)ceilf(sev * 4.f);
    int el = (ar >= 4.f) ? 1 : 0;
    GTC q;
    q.gx = gx; q.gy = gy;
    q.ct = cosf(-th); q.st = sinf(-th);
    q.w15 = w * 1.5f; q.h15 = h * 1.5f;
    float sc = sqrtf(w * h);
    float is = 1.f / (sc + 1e-6f);         q.inv_s2  = is * is;
    float isc = 1.f / (sc * 1.5f + 1e-6f); q.inv_sc2 = isc * isc;
    float strength = fminf(fmaxf((ar - 4.f) / (4.f + EPSF), 0.f), 1.f);
    q.factor = (1.f + sev * (4.f / 13.f)) * (1.f + 0.25f * strength);
    q.gth = th;
    q.budget = 13 + te + el;
    q.fbk = te + el + 3;
    int fl = (mg[bg] > 0.f) ? 1 : 0;
    if ((area < 0.01f) || (ar >= 4.f)) fl |= 2;
    q.flags = fl;
    q.lbl = gl[bg];
    if (!(fl & 1)) q.factor = 0.f;   // masked GT: body yields exactly 0
    q.pad0 = 0.f; q.pad1 = 0.f;
    d_gt[bg] = q;
    d_cnt[bg] = 0;
}

// ---------------------------------------------------------------------------
// A: block = (512-anchor tile, b), 256 threads, 2 anchors/thread.
// Straight-line g-loop, float2 am stores, grid 17x16 = 272.
// ---------------------------------------------------------------------------
__global__ __launch_bounds__(256) void pair_kernel(const float4* __restrict__ anch4,
                                                   const float* __restrict__ ps,
                                                   const float* __restrict__ pbx) {
    int b   = blockIdx.y;
    int tid = threadIdx.x;
    int n0  = blockIdx.x * 512 + tid * 2;

    __shared__ GTC           s_gt[GG];     // 8 KB
    __shared__ unsigned char s_any[GG];

    {
        const float4* src = (const float4*)(d_gt + b * GG);
        float4*       dst = (float4*)s_gt;
        dst[tid]       = src[tid];
        dst[tid + 256] = src[tid + 256];
        if (tid < GG) s_any[tid] = 0;
    }
    __syncthreads();

    bool valid = (n0 < NN);   // NN even, n0 even -> pair all-or-nothing
    float ax0 = 0.f, ay0 = 0.f, px0 = 0.f, py0 = 0.f, pt0 = 0.f;
    float ax1 = 0.f, ay1 = 0.f, px1 = 0.f, py1 = 0.f, pt1 = 0.f;
    float l00 = 0.f, l01 = 0.f, l02 = 0.f, l03 = 0.f, l04 = 0.f;
    float l10 = 0.f, l11 = 0.f, l12 = 0.f, l13 = 0.f, l14 = 0.f;
    if (valid) {
        float4 a = anch4[n0 >> 1];
        ax0 = a.x; ay0 = a.y; ax1 = a.z; ay1 = a.w;
        size_t base = (size_t)(b * NN + n0) * 5;
        px0 = pbx[base];     py0 = pbx[base + 1]; pt0 = pbx[base + 4];
        px1 = pbx[base + 5]; py1 = pbx[base + 6]; pt1 = pbx[base + 9];
#define LC(d, i) { float sg = 1.f/(1.f+__expf(-ps[base+(i)])); \
                   sg = fminf(fmaxf(sg, EPSF), 1.f); d = 0.5f*__logf(sg+EPSF); }
        LC(l00,0) LC(l01,1) LC(l02,2) LC(l03,3) LC(l04,4)
        LC(l10,5) LC(l11,6) LC(l12,7) LC(l13,8) LC(l14,9)
#undef LC
    }

    float bv0 = 0.f, bv1 = 0.f;
    int   bg0 = 0,   bg1 = 0;
    float* amp = d_am + (size_t)b * GG * NN + n0;

    for (int g = 0; g < GG; g++) {
        GTC q = s_gt[g];
        int lb = q.lbl;

        float dxa0 = ax0 - q.gx, dya0 = ay0 - q.gy;
        float dxa1 = ax1 - q.gx, dya1 = ay1 - q.gy;
        float lx0 = dxa0 * q.ct - dya0 * q.st, ly0 = dxa0 * q.st + dya0 * q.ct;
        float lx1 = dxa1 * q.ct - dya1 * q.st, ly1 = dxa1 * q.st + dya1 * q.ct;
        bool in0 = valid && (fabsf(lx0) < q.w15) && (fabsf(ly0) < q.h15);
        bool in1 = valid && (fabsf(lx1) < q.w15) && (fabsf(ly1) < q.h15);

        float dxp0 = px0 - q.gx, dyp0 = py0 - q.gy;
        float dxp1 = px1 - q.gx, dyp1 = py1 - q.gy;
        float t0 = (dxp0 * dxp0 + dyp0 * dyp0) * q.inv_s2;
        float t1 = (dxp1 * dxp1 + dyp1 * dyp1) * q.inv_s2;
        float x0 = __expf(-t0) + EPSF;
        float x1 = __expf(-t1) + EPSF;
        float x0s = x0 * x0; float x06 = x0s * x0s * x0s;
        float x1s = x1 * x1; float x16 = x1s * x1s * x1s;
        float wv0 = (pt0 - q.gth) + HPI_F;
        float wv1 = (pt1 - q.gth) + HPI_F;
        wv0 -= PI_F * floorf(wv0 * IPI_F);
        wv1 -= PI_F * floorf(wv1 * IPI_F);
        float wr0 = fabsf(wv0 - HPI_F);
        float wr1 = fabsf(wv1 - HPI_F);
        float c0 = (dxa0 * dxa0 + dya0 * dya0) * q.inv_sc2;
        float c1 = (dxa1 * dxa1 + dya1 * dya1) * q.inv_sc2;
        float lcl0 = lb == 0 ? l00 : (lb == 1 ? l01 : (lb == 2 ? l02 : (lb == 3 ? l03 : l04)));
        float lcl1 = lb == 0 ? l10 : (lb == 1 ? l11 : (lb == 2 ? l12 : (lb == 3 ? l13 : l14)));
        float val0 = fmaxf(q.factor * x06 * __expf(lcl0 - 1.5f * wr0 - c0), 0.f);
        float val1 = fmaxf(q.factor * x16 * __expf(lcl1 - 1.5f * wr1 - c1), 0.f);
        float vv0 = in0 ? val0 : 0.f;
        float vv1 = in1 ? val1 : 0.f;

        if (in0 || in1) s_any[g] = 1;
        if (valid) *(float2*)(amp + (size_t)g * NN) = make_float2(vv0, vv1);
        if (vv0 > bv0) { bv0 = vv0; bg0 = g; }
        if (vv1 > bv1) { bv1 = vv1; bg1 = g; }
    }
    __syncthreads();
    if (tid < GG && s_any[tid]) atomicOr(&d_cnt[b * GG + tid], 1);
    if (valid) {
        int idx = b * NN + n0;
        d_best[idx]     = ((u64)__float_as_uint(bv0) << 32) | (unsigned)(127 - bg0);
        d_best[idx + 1] = ((u64)__float_as_uint(bv1) << 32) | (unsigned)(127 - bg1);
        d_norm[idx] = 0; d_norm[idx + 1] = 0;
        d_pos[idx] = 0;  d_pos[idx + 1] = 0;
    }
}

// ---------------------------------------------------------------------------
// B (pinned): block per (b,g). Copy row + column maxima in one pass, then
// warp-0-only 18-round extraction. Column c holds i = c + k*256, n = 4i+j.
// ---------------------------------------------------------------------------
__global__ __launch_bounds__(256) void topk_kernel(const float2* __restrict__ anch,
                                                   const float* __restrict__ ps,
                                                   const float* __restrict__ pbx) {
    int bg = blockIdx.x;
    int b  = bg >> 7;
    GTC q = d_gt[bg];
    if (!(q.flags & 1)) return;

    int tid = threadIdx.x, lane = tid & 31, wid = tid >> 5;

    __shared__ float    s_av[NN];          // 33.6 KB
    __shared__ u64      s_cmax[256];
    __shared__ u64      s_rm[256];
    __shared__ u64      s_red[8];
    __shared__ unsigned s_chosen[8];

    const float4* am4 = (const float4*)(d_am + (size_t)bg * NN);
    float4*       av4 = (float4*)s_av;
    bool fb = (d_cnt[bg] == 0) && (q.flags & 2);

    u64 cm = 0;
    for (int i = tid; i < NQ4; i += 256) {
        float4 v = am4[i];
        av4[i] = v;
        float m4 = fmaxf(fmaxf(v.x, v.y), fmaxf(v.z, v.w));
        int j = (v.x == m4) ? 0 : ((v.y == m4) ? 1 : ((v.z == m4) ? 2 : 3));
        u64 key = ((u64)__float_as_uint(m4) << 32) | (unsigned)(16384 - (4 * i + j));
        if (key > cm) cm = key;
    }
    s_rm[tid] = 0;

    // -------- tiny/elongated fallback (rare) --------
    if (fb) {
        __syncthreads();
        for (int r = 0; r < 8; r++) {
            u64 key = 0xFFFFFFFFFFFFFFFFull;
            for (int n = tid; n < NN; n += 256) {
                bool skip = false;
                for (int qq = 0; qq < r; qq++)
                    if (s_chosen[qq] == (unsigned)n) skip = true;
                if (!skip) {
                    float2 a = anch[n];
                    float dx = a.x - q.gx, dy = a.y - q.gy;
                    float d2 = dx * dx + dy * dy;
                    u64 k = ((u64)__float_as_uint(d2) << 32) | (unsigned)n;
                    if (k < key) key = k;
                }
            }
#pragma unroll
            for (int o = 16; o; o >>= 1) {
                u64 t = __shfl_xor_sync(0xffffffffu, key, o);
                if (t < key) key = t;
            }
            if (lane == 0) s_red[wid] = key;
            __syncthreads();
            if (wid == 0) {
                u64 v = (lane < 8) ? s_red[lane] : 0xFFFFFFFFFFFFFFFFull;
#pragma unroll
                for (int o = 4; o; o >>= 1) {
                    u64 t = __shfl_xor_sync(0xffffffffu, v, o);
                    if (t < v) v = t;
                }
                if (lane == 0) s_chosen[r] = (unsigned)(v & 0xffffffffu);
            }
            __syncthreads();
            unsigned nw = s_chosen[r];
            if (r < q.fbk && (int)(nw & 255u) == tid) {
                int n = (int)nw;
                float2 a = anch[n];
                float dxa = a.x - q.gx, dya = a.y - q.gy;
                size_t base = (size_t)(b * NN + n) * 5;
                float dxp = pbx[base] - q.gx, dyp = pbx[base + 1] - q.gy;
                float t = (dxp * dxp + dyp * dyp) * q.inv_s2;
                float x = __expf(-t) + EPSF;
                float x2 = x * x; float x6 = x2 * x2 * x2;
                float wv = (pbx[base + 4] - q.gth) + HPI_F;
                wv -= PI_F * floorf(wv * IPI_F);
                float wr = fabsf(wv - HPI_F);
                float c = (dxa * dxa + dya * dya) * q.inv_sc2;
                float sg = 1.f / (1.f + __expf(-ps[base + q.lbl]));
                sg = fminf(fmaxf(sg, EPSF), 1.f);
                float lcl = 0.5f * __logf(sg + EPSF);
                float v = fmaxf(q.factor * x6 * __expf(lcl - 1.5f * wr - c), 0.f);
                s_av[n] = v;
                u64 bk = ((u64)__float_as_uint(v) << 32) | (unsigned)(127 - (bg & 127));
                atomicMax((u64*)(d_best + b * NN + n), bk);
            }
            __syncthreads();
        }
        // recompute column maxima after patches
        cm = 0;
        for (int i = tid; i < NQ4; i += 256) {
            float4 v = av4[i];
            float m4 = fmaxf(fmaxf(v.x, v.y), fmaxf(v.z, v.w));
            int j = (v.x == m4) ? 0 : ((v.y == m4) ? 1 : ((v.z == m4) ? 2 : 3));
            u64 key = ((u64)__float_as_uint(m4) << 32) | (unsigned)(16384 - (4 * i + j));
            if (key > cm) cm = key;
        }
    }

    s_cmax[tid] = cm;
    __syncthreads();
    if (wid != 0) return;

    // -------- warp-0-only 18-round extraction --------
    u64 myk[8];
#pragma unroll
    for (int j2 = 0; j2 < 8; j2++) myk[j2] = s_cmax[lane * 8 + j2];
    u64 topkey = 0;

    for (int r = 0; r < MAXTK; r++) {
        u64 m = myk[0];
#pragma unroll
        for (int j2 = 1; j2 < 8; j2++) if (myk[j2] > m) m = myk[j2];
        unsigned hi = (unsigned)(m >> 32);
        unsigned hmax = __reduce_max_sync(0xffffffffu, hi);
        unsigned lo = (hi == hmax) ? (unsigned)m : 0u;
        unsigned lmax = __reduce_max_sync(0xffffffffu, lo);
        if (lane == r) topkey = ((u64)hmax << 32) | lmax;

        int bn = 16384 - (int)lmax;
        int bi = bn >> 2;
        int c  = bi & 255;
        int mi = ((bi >> 8) << 2) | (bn & 3);
        if (lane == 0) s_rm[c] |= (1ull << mi);
        __syncwarp();
        u64 rmm = s_rm[c];
        int nv = (c < (NQ4 & 255)) ? 36 : 32;
        u64 nk = 0;
        {
            int mm = lane;
            if (!((rmm >> mm) & 1ull)) {
                int n2 = 4 * (c + (mm >> 2) * 256) + (mm & 3);
                nk = ((u64)__float_as_uint(s_av[n2]) << 32) | (unsigned)(16384 - n2);
            }
            if (nv == 36 && lane < 4) {
                int mm2 = 32 + lane;
                if (!((rmm >> mm2) & 1ull)) {
                    int n2 = 4 * (c + (mm2 >> 2) * 256) + (mm2 & 3);
                    u64 k2 = ((u64)__float_as_uint(s_av[n2]) << 32) | (unsigned)(16384 - n2);
                    if (k2 > nk) nk = k2;
                }
            }
        }
        unsigned h2 = (unsigned)(nk >> 32);
        unsigned hm2 = __reduce_max_sync(0xffffffffu, h2);
        unsigned lo2 = (h2 == hm2) ? (unsigned)nk : 0u;
        unsigned lm2 = __reduce_max_sync(0xffffffffu, lo2);
        u64 newmax = ((u64)hm2 << 32) | lm2;
        if (lane == (c >> 3)) {
            switch (c & 7) {
                case 0: myk[0] = newmax; break;
                case 1: myk[1] = newmax; break;
                case 2: myk[2] = newmax; break;
                case 3: myk[3] = newmax; break;
                case 4: myk[4] = newmax; break;
                case 5: myk[5] = newmax; break;
                case 6: myk[6] = newmax; break;
                case 7: myk[7] = newmax; break;
            }
        }
    }

    // -------- epilogue (warp 0) --------
    {
        float val = 0.f; unsigned nj = 0; float ovj = 0.f;
        if (lane < MAXTK) {
            val = __uint_as_float((unsigned)(topkey >> 32));
            nj = 16384u - (unsigned)(topkey & 0xffffffffull);
            size_t base = (size_t)(b * NN + nj) * 5;
            float dx = pbx[base] - q.gx, dy = pbx[base + 1] - q.gy;
            float t = (dx * dx + dy * dy) * q.inv_s2;
            ovj = fminf(fmaxf(__expf(-t), 0.f), 1.f);
        }
        float s = ovj;
#pragma unroll
        for (int o = 16; o; o >>= 1) s += __shfl_xor_sync(0xffffffffu, s, o);
        float dk = rintf(s);
        dk = fmaxf(dk, 1.f);
        dk = fminf(dk, (float)q.budget);
        int dyn = (int)dk;
        bool sel = (lane < MAXTK) && (val > EPSF) && (lane < dyn);
        unsigned bal = __ballot_sync(0xffffffffu, sel);
        if (bal) {
            int first = __ffs(bal) - 1;
            float maxalign = __shfl_sync(0xffffffffu, val, first);
            float mo = sel ? ovj : 0.f;
#pragma unroll
            for (int o = 16; o; o >>= 1) mo = fmaxf(mo, __shfl_xor_sync(0xffffffffu, mo, o));
            if (sel) {
                float nv2 = val * mo / (maxalign + EPSF);
                atomicMax(d_norm + b * NN + nj, __float_as_int(nv2));
                d_pos[b * NN + nj] = 1;
            }
        }
    }
}

// ---------------------------------------------------------------------------
__global__ __launch_bounds__(256) void out_kernel(const int* __restrict__ gl,
                                                  const float* __restrict__ gb,
                                                  float* __restrict__ out) {
    int idx = blockIdx.x * 256 + threadIdx.x;
    if (idx >= BN) return;
    int b = idx / NN;
    u64 key = d_best[idx];
    int g = 127 - (int)(key & 0xffffffffull);
    bool pos = d_pos[idx] != 0;
    int lab = gl[b * GG + g];
    out[idx] = pos ? (float)lab : 5.f;
    const float* gp = gb + (size_t)(b * GG + g) * 5;
    float* ob = out + BN + (size_t)idx * 5;
    ob[0] = gp[0]; ob[1] = gp[1]; ob[2] = gp[2]; ob[3] = gp[3]; ob[4] = gp[4];
    float nv = __int_as_float(d_norm[idx]);
    float* os = out + (size_t)BN * 6 + (size_t)idx * 5;
#pragma unroll
    for (int c = 0; c < 5; c++) os[c] = (pos && c == lab) ? nv : 0.f;
    out[(size_t)BN * 11 + idx] = pos ? 1.f : 0.f;
}

// ---------------------------------------------------------------------------
extern "C" void kernel_launch(void* const* d_in, const int* in_sizes, int n_in,
                              void* d_out, int out_size) {
    const float* ps  = (const float*)d_in[0];
    const float* pbx = (const float*)d_in[1];
    const float* ap  = (const float*)d_in[2];
    const int*   gl  = (const int*)d_in[3];
    const float* gbx = (const float*)d_in[4];
    const float* mg  = (const float*)d_in[5];

    prep_gt<<<(BGT + 255) / 256, 256>>>(gl, gbx, mg);
    dim3 ga((NN + 511) / 512, BB);
    pair_kernel<<<ga, 256>>>((const float4*)ap, ps, pbx);
    topk_kernel<<<BGT, 256>>>((const float2*)ap, ps, pbx);
    out_kernel<<<(BN + 255) / 256, 256>>>(gl, gbx, (float*)d_out);
}